// round 4
// baseline (speedup 1.0000x reference)
#include <cuda_runtime.h>

#define CCH    64
#define HWDIM  64
#define NPIX   4096
#define CKK1   577                 // Cin*K*K + 1 (bias col)
#define EMB_ROW (CCH * CKK1)       // 36928 floats per bucket
#define NT     216
#define PXT    32
#define MAXCH  352                 // >= worst-case sum ceil(cnt/32)
#define ROWSTR 580
#define PSTR   580
#define SSTR   36
#define WTSTR  65

// ---- scratch (allocation-free rule: device globals) ----
__device__ float g_h[CCH * NPIX];
__device__ int   g_pix[NPIX];
__device__ int   g_chunk_bucket[MAXCH];
__device__ int   g_chunk_base[MAXCH];
__device__ int   g_chunk_cnt[MAXCH];
__device__ int   g_nchunks;

// packed fp32x2 FMA (Blackwell packed pipe; PTX-only)
__device__ __forceinline__ unsigned long long ffma2(unsigned long long a,
                                                    unsigned long long b,
                                                    unsigned long long c) {
    unsigned long long d;
    asm("fma.rn.f32x2 %0, %1, %2, %3;" : "=l"(d) : "l"(a), "l"(b), "l"(c));
    return d;
}
__device__ __forceinline__ float hadd2(unsigned long long a) {
    return __uint_as_float((unsigned)(a & 0xffffffffu)) +
           __uint_as_float((unsigned)(a >> 32));
}

// ---------------------------------------------------------------------------
// body1: grouped 3x3 conv + bias + ReLU, smem-tiled.
// CTA = (group g, 4-row band, 8-out-channel half). Grid 128, 256 threads.
// ---------------------------------------------------------------------------
__global__ void __launch_bounds__(256)
body1_kernel(const float* __restrict__ x,
             const float* __restrict__ w1,
             const float* __restrict__ b1) {
    __shared__ float tile[16][6][66];   // 16 in-ch, 6 rows (halo), 66 cols (pad)
    __shared__ float w_s[8 * 144];

    int bid  = blockIdx.x;
    int g    = bid & 3;
    int half = (bid >> 2) & 1;
    int band = bid >> 3;                // 0..15
    int y0   = band * 4;
    int ochb = g * 16 + half * 8;
    int tid  = threadIdx.x;

    for (int i = tid; i < 16 * 6; i += 256) {
        int ch = i / 6, r = i - ch * 6;
        tile[ch][r][0] = 0.0f; tile[ch][r][65] = 0.0f;
    }
    for (int i = tid; i < 16 * 6 * 64; i += 256) {
        int ch  = i / 384;
        int rem = i - ch * 384;
        int r   = rem >> 6;
        int xx  = rem & 63;
        int yy  = y0 + r - 1;
        tile[ch][r][xx + 1] = ((unsigned)yy < (unsigned)HWDIM)
            ? x[(g * 16 + ch) * NPIX + yy * HWDIM + xx] : 0.0f;
    }
    for (int i = tid; i < 8 * 144; i += 256) w_s[i] = w1[ochb * 144 + i];
    __syncthreads();

    int j  = tid >> 6;      // row in band
    int xx = tid & 63;
    float acc[8];
    #pragma unroll
    for (int o = 0; o < 8; ++o) acc[o] = b1[ochb + o];

    for (int ic = 0; ic < 16; ++ic) {
        #pragma unroll
        for (int ky = 0; ky < 3; ++ky) {
            float v0 = tile[ic][j + ky][xx];
            float v1 = tile[ic][j + ky][xx + 1];
            float v2 = tile[ic][j + ky][xx + 2];
            #pragma unroll
            for (int o = 0; o < 8; ++o) {
                const float* wp = &w_s[o * 144 + ic * 9 + ky * 3];
                acc[o] = fmaf(wp[0], v0, fmaf(wp[1], v1, fmaf(wp[2], v2, acc[o])));
            }
        }
    }
    #pragma unroll
    for (int o = 0; o < 8; ++o)
        g_h[(ochb + o) * NPIX + (y0 + j) * HWDIM + xx] = fmaxf(acc[o], 0.0f);
}

// ---------------------------------------------------------------------------
// prep: histogram + scan + chunk list + scatter, one 256-thread CTA.
// ---------------------------------------------------------------------------
__global__ void prep_kernel(const int* __restrict__ buckets) {
    __shared__ int cnt[256], scn[256], offs[256], fil[256], chs[256];
    int tid = threadIdx.x;
    cnt[tid] = 0; fil[tid] = 0;
    __syncthreads();
    for (int p = tid; p < NPIX; p += 256) atomicAdd(&cnt[buckets[p]], 1);
    __syncthreads();

    scn[tid] = cnt[tid];
    __syncthreads();
    for (int d = 1; d < 256; d <<= 1) {
        int v = (tid >= d) ? scn[tid - d] : 0;
        __syncthreads();
        scn[tid] += v;
        __syncthreads();
    }
    int myoff = scn[tid] - cnt[tid];
    offs[tid] = myoff;

    int nch = (tid < NT) ? ((cnt[tid] + PXT - 1) >> 5) : 0;
    chs[tid] = nch;
    __syncthreads();
    for (int d = 1; d < 256; d <<= 1) {
        int v = (tid >= d) ? chs[tid - d] : 0;
        __syncthreads();
        chs[tid] += v;
        __syncthreads();
    }
    int chbase = chs[tid] - nch;
    if (tid < NT) {
        int c = cnt[tid];
        for (int jj = 0; jj < nch; ++jj) {
            g_chunk_bucket[chbase + jj] = tid;
            g_chunk_base[chbase + jj]   = myoff + jj * PXT;
            g_chunk_cnt[chbase + jj]    = min(PXT, c - jj * PXT);
        }
    }
    if (tid == 255) g_nchunks = chs[255];
    __syncthreads();

    for (int p = tid; p < NPIX; p += 256) {
        int b = buckets[p];
        int pos = offs[b] + atomicAdd(&fil[b], 1);
        g_pix[pos] = p;
    }
}

// ---------------------------------------------------------------------------
// dyn: one CTA per (bucket, <=32-px chunk). 128 threads.
//   - 64 filter rows + 32 patches resident in smem
//   - 4 rows x 4 px tile per thread, packed f32x2 FMA over column pairs
//   - fused ReLU -> 1x1 conv -> residual -> ReLU
// ---------------------------------------------------------------------------
__global__ void __launch_bounds__(128)
dyn_kernel(const float* __restrict__ emb,
           const float* __restrict__ w2,
           const float* __restrict__ b2,
           const float* __restrict__ x,
           float*       __restrict__ out) {
    extern __shared__ __align__(16) float smem[];
    float* rows_s  = smem;                         // 64*580
    float* patch_s = smem + 64 * ROWSTR;           // 32*580
    float* srel    = patch_s;                      // overlay after compute
    float* wT      = rows_s;                       // overlay after compute
    int*   pixl    = (int*)(patch_s + PXT * PSTR);

    int bid = blockIdx.x;
    if (bid >= g_nchunks) return;
    int bkt  = g_chunk_bucket[bid];
    int base = g_chunk_base[bid];
    int npx  = g_chunk_cnt[bid];

    int tid  = threadIdx.x;
    int rowg = tid & 15;      // rows rowg + 16j, j<4
    int pxg  = tid >> 4;      // px 4*pxg + i, i<4

    if (tid < PXT) pixl[tid] = (tid < npx) ? g_pix[base + tid] : 0;
    __syncthreads();

    // --- stage 64 filter rows: float4 LDG + division-free scatter ---
    {
        const float4* embb4 = (const float4*)(emb + (size_t)bkt * EMB_ROW);
        int r = 0, c = tid << 2;                  // e = 4*tid < 577 -> r=0
        #pragma unroll 4
        for (int i4 = tid; i4 < EMB_ROW / 4; i4 += 128) {
            float4 v = __ldg(embb4 + i4);
            float el[4] = {v.x, v.y, v.z, v.w};
            #pragma unroll
            for (int m = 0; m < 4; ++m) {
                int cc = c + m, rr = r;
                if (cc >= CKK1) { cc -= CKK1; rr++; }
                rows_s[rr * ROWSTR + cc] = el[m];
            }
            c += 512;
            if (c >= CKK1) { c -= CKK1; r++; }
        }
    }

    // --- build patches (order cin*9 + ky*3 + kx; col 576 = bias 1.0) ---
    for (int px = 0; px < PXT; ++px) {
        int p = pixl[px];
        int y = p >> 6, xpix = p & 63;
        bool valid = (px < npx);
        for (int i = tid; i < CKK1; i += 128) {
            float v = 0.0f;
            if (valid) {
                if (i == CKK1 - 1) v = 1.0f;
                else {
                    int cin = i / 9;
                    int rr  = i - cin * 9;
                    int ky  = rr / 3, kx = rr - ky * 3;
                    int yy  = y + ky - 1, x2 = xpix + kx - 1;
                    if ((unsigned)yy < (unsigned)HWDIM && (unsigned)x2 < (unsigned)HWDIM)
                        v = g_h[cin * NPIX + yy * HWDIM + x2];
                }
            }
            patch_s[px * PSTR + i] = v;
        }
    }
    __syncthreads();

    // --- dynamic conv: 4 rows x 4 px, f32x2-packed over column pairs ---
    unsigned long long acc[4][4];
    #pragma unroll
    for (int j = 0; j < 4; ++j)
        #pragma unroll
        for (int i = 0; i < 4; ++i) acc[j][i] = 0ull;

    #pragma unroll 2
    for (int c4 = 0; c4 < 144; ++c4) {           // cols 0..575
        ulonglong2 r[4], p[4];
        #pragma unroll
        for (int j = 0; j < 4; ++j)
            r[j] = *(const ulonglong2*)(rows_s + (rowg + 16 * j) * ROWSTR + (c4 << 2));
        #pragma unroll
        for (int i = 0; i < 4; ++i)
            p[i] = *(const ulonglong2*)(patch_s + (4 * pxg + i) * PSTR + (c4 << 2));
        #pragma unroll
        for (int j = 0; j < 4; ++j)
            #pragma unroll
            for (int i = 0; i < 4; ++i) {
                acc[j][i] = ffma2(r[j].x, p[i].x, acc[j][i]);
                acc[j][i] = ffma2(r[j].y, p[i].y, acc[j][i]);
            }
    }

    // horizontal add + bias column (576)
    float sres[4][4];
    #pragma unroll
    for (int j = 0; j < 4; ++j) {
        int row = rowg + 16 * j;
        float rb = rows_s[row * ROWSTR + 576];
        #pragma unroll
        for (int i = 0; i < 4; ++i) {
            int px = 4 * pxg + i;
            float s = hadd2(acc[j][i]);
            sres[j][i] = fmaf(rb, patch_s[px * PSTR + 576], s);
        }
    }

    __syncthreads();   // all smem reads done before overlays

    #pragma unroll
    for (int j = 0; j < 4; ++j)
        #pragma unroll
        for (int i = 0; i < 4; ++i)
            srel[(rowg + 16 * j) * SSTR + 4 * pxg + i] = fmaxf(sres[j][i], 0.0f);

    // stage w2 transposed: wT[k*WTSTR + oc] = w2[oc*64 + k]
    for (int i = tid; i < CCH * CCH; i += 128) {
        int oc = i >> 6, k = i & 63;
        wT[k * WTSTR + oc] = __ldg(w2 + i);
    }
    __syncthreads();

    // --- 1x1 conv + bias + residual + final ReLU ---
    int ocg  = tid & 31;
    int pxg1 = tid >> 5;
    float accA[8], accB[8];
    float bA = b2[ocg], bB = b2[ocg + 32];
    #pragma unroll
    for (int jj = 0; jj < 8; ++jj) { accA[jj] = bA; accB[jj] = bB; }

    const float4* srl = (const float4*)(srel + pxg1 * 8);
    #pragma unroll 4
    for (int k = 0; k < CCH; ++k) {
        float wa = wT[k * WTSTR + ocg];
        float wb = wT[k * WTSTR + ocg + 32];
        float4 s0 = srl[k * (SSTR / 4)];
        float4 s1 = srl[k * (SSTR / 4) + 1];
        accA[0] = fmaf(wa, s0.x, accA[0]); accB[0] = fmaf(wb, s0.x, accB[0]);
        accA[1] = fmaf(wa, s0.y, accA[1]); accB[1] = fmaf(wb, s0.y, accB[1]);
        accA[2] = fmaf(wa, s0.z, accA[2]); accB[2] = fmaf(wb, s0.z, accB[2]);
        accA[3] = fmaf(wa, s0.w, accA[3]); accB[3] = fmaf(wb, s0.w, accB[3]);
        accA[4] = fmaf(wa, s1.x, accA[4]); accB[4] = fmaf(wb, s1.x, accB[4]);
        accA[5] = fmaf(wa, s1.y, accA[5]); accB[5] = fmaf(wb, s1.y, accB[5]);
        accA[6] = fmaf(wa, s1.z, accA[6]); accB[6] = fmaf(wb, s1.z, accB[6]);
        accA[7] = fmaf(wa, s1.w, accA[7]); accB[7] = fmaf(wb, s1.w, accB[7]);
    }
    #pragma unroll
    for (int jj = 0; jj < 8; ++jj) {
        int px = pxg1 * 8 + jj;
        if (px < npx) {
            int p   = pixl[px];
            int oiA = ocg * NPIX + p;
            int oiB = (ocg + 32) * NPIX + p;
            out[oiA] = fmaxf(accA[jj] + x[oiA], 0.0f);
            out[oiB] = fmaxf(accB[jj] + x[oiB], 0.0f);
        }
    }
}

// ---------------------------------------------------------------------------
extern "C" void kernel_launch(void* const* d_in, const int* in_sizes, int n_in,
                              void* d_out, int out_size) {
    const float* x       = (const float*)d_in[0];
    const int*   buckets = (const int*)  d_in[1];
    const float* w1      = (const float*)d_in[2];
    const float* b1      = (const float*)d_in[3];
    const float* emb     = (const float*)d_in[4];
    const float* w2      = (const float*)d_in[5];
    const float* b2      = (const float*)d_in[6];
    float*       out     = (float*)d_out;

    const int smem_bytes = (64 * ROWSTR + PXT * PSTR) * 4 + PXT * 4; // 222,848 B
    cudaFuncSetAttribute(dyn_kernel,
                         cudaFuncAttributeMaxDynamicSharedMemorySize, smem_bytes);

    body1_kernel<<<128, 256>>>(x, w1, b1);
    prep_kernel<<<1, 256>>>(buckets);
    dyn_kernel<<<MAXCH, 128, smem_bytes>>>(emb, w2, b2, x, out);
}

// round 10
// speedup vs baseline: 1.5842x; 1.5842x over previous
#include <cuda_runtime.h>

#define CCH    64
#define HWDIM  64
#define NPIX   4096
#define CKK1   577                 // Cin*K*K + 1 (bias col)
#define EMB_ROW (CCH * CKK1)
#define NT     216
#define PXT    32
#define MAXCH  352
#define ROWSTR 580
#define PSTR   580
#define SSTR   36
#define WTSTR  65

// ---- scratch (allocation-free rule: device globals) ----
__device__ float g_h[CCH * NPIX];
__device__ int   g_pix[NPIX];
__device__ int   g_chunk_bucket[MAXCH];
__device__ int   g_chunk_base[MAXCH];
__device__ int   g_chunk_cnt[MAXCH];
__device__ int   g_nchunks;

__device__ __forceinline__ unsigned long long ffma2(unsigned long long a,
                                                    unsigned long long b,
                                                    unsigned long long c) {
    unsigned long long d;
    asm("fma.rn.f32x2 %0, %1, %2, %3;" : "=l"(d) : "l"(a), "l"(b), "l"(c));
    return d;
}
__device__ __forceinline__ float hadd2(unsigned long long a) {
    return __uint_as_float((unsigned)(a & 0xffffffffu)) +
           __uint_as_float((unsigned)(a >> 32));
}

// ---------------------------------------------------------------------------
// body1: grouped 3x3 conv + bias + ReLU. 256 CTAs (2-row bands), 128 threads,
// unrolled staging for DRAM MLP.
// ---------------------------------------------------------------------------
__global__ void __launch_bounds__(128)
body1_kernel(const float* __restrict__ x,
             const float* __restrict__ w1,
             const float* __restrict__ b1) {
    __shared__ float tile[16][4][66];
    __shared__ float w_s[8 * 144];

    int bid  = blockIdx.x;
    int g    = bid & 3;
    int half = (bid >> 2) & 1;
    int band = bid >> 3;                // 0..31
    int y0   = band * 2;
    int ochb = g * 16 + half * 8;
    int tid  = threadIdx.x;

    for (int i = tid; i < 16 * 4; i += 128) {
        int ch = i >> 2, r = i & 3;
        tile[ch][r][0] = 0.0f; tile[ch][r][65] = 0.0f;
    }
    #pragma unroll 8
    for (int i = tid; i < 16 * 4 * 64; i += 128) {
        int ch  = i >> 8;
        int rem = i & 255;
        int r   = rem >> 6;
        int xx  = rem & 63;
        int yy  = y0 + r - 1;
        tile[ch][r][xx + 1] = ((unsigned)yy < (unsigned)HWDIM)
            ? x[(g * 16 + ch) * NPIX + yy * HWDIM + xx] : 0.0f;
    }
    #pragma unroll 4
    for (int i = tid; i < 8 * 144; i += 128) w_s[i] = w1[ochb * 144 + i];
    __syncthreads();

    int j  = tid >> 6;     // 0..1
    int xx = tid & 63;
    float acc[8];
    #pragma unroll
    for (int o = 0; o < 8; ++o) acc[o] = b1[ochb + o];

    for (int ic = 0; ic < 16; ++ic) {
        #pragma unroll
        for (int ky = 0; ky < 3; ++ky) {
            float v0 = tile[ic][j + ky][xx];
            float v1 = tile[ic][j + ky][xx + 1];
            float v2 = tile[ic][j + ky][xx + 2];
            #pragma unroll
            for (int o = 0; o < 8; ++o) {
                const float* wp = &w_s[o * 144 + ic * 9 + ky * 3];
                acc[o] = fmaf(wp[0], v0, fmaf(wp[1], v1, fmaf(wp[2], v2, acc[o])));
            }
        }
    }
    #pragma unroll
    for (int o = 0; o < 8; ++o)
        g_h[(ochb + o) * NPIX + (y0 + j) * HWDIM + xx] = fmaxf(acc[o], 0.0f);
}

// ---------------------------------------------------------------------------
// prep: histogram + scan + chunk list + scatter, one 256-thread CTA.
// ---------------------------------------------------------------------------
__global__ void prep_kernel(const int* __restrict__ buckets) {
    __shared__ int cnt[256], scn[256], offs[256], fil[256], chs[256];
    int tid = threadIdx.x;
    cnt[tid] = 0; fil[tid] = 0;
    __syncthreads();
    for (int p = tid; p < NPIX; p += 256) atomicAdd(&cnt[buckets[p]], 1);
    __syncthreads();

    scn[tid] = cnt[tid];
    __syncthreads();
    for (int d = 1; d < 256; d <<= 1) {
        int v = (tid >= d) ? scn[tid - d] : 0;
        __syncthreads();
        scn[tid] += v;
        __syncthreads();
    }
    int myoff = scn[tid] - cnt[tid];
    offs[tid] = myoff;

    int nch = (tid < NT) ? ((cnt[tid] + PXT - 1) >> 5) : 0;
    chs[tid] = nch;
    __syncthreads();
    for (int d = 1; d < 256; d <<= 1) {
        int v = (tid >= d) ? chs[tid - d] : 0;
        __syncthreads();
        chs[tid] += v;
        __syncthreads();
    }
    int chbase = chs[tid] - nch;
    if (tid < NT) {
        int c = cnt[tid];
        for (int jj = 0; jj < nch; ++jj) {
            g_chunk_bucket[chbase + jj] = tid;
            g_chunk_base[chbase + jj]   = myoff + jj * PXT;
            g_chunk_cnt[chbase + jj]    = min(PXT, c - jj * PXT);
        }
    }
    if (tid == 255) g_nchunks = chs[255];
    __syncthreads();

    for (int p = tid; p < NPIX; p += 256) {
        int b = buckets[p];
        int pos = offs[b] + atomicAdd(&fil[b], 1);
        g_pix[pos] = p;
    }
}

// ---------------------------------------------------------------------------
// dyn: one CTA per (bucket, <=32-px chunk). 128 threads.
//   - 8 rows x 8 px per-thread tile (packed f32x2), warps split K 4-way
//   - lane = (ps<<3)|rs: phases see 8 distinct rows (conflict-free) and
//     broadcast px -> crossbar ~64 cyc/warp/c4, balanced with FFMA2 issue
//   - K-partials reduced via smem (rows region, dead after compute)
//   - fused ReLU -> 1x1 conv -> residual -> ReLU
// ---------------------------------------------------------------------------
__global__ void __launch_bounds__(128)
dyn_kernel(const float* __restrict__ emb,
           const float* __restrict__ w2,
           const float* __restrict__ b2,
           const float* __restrict__ x,
           float*       __restrict__ out) {
    extern __shared__ __align__(16) float smem[];
    float* rows_s  = smem;                           // 64*580
    float* patch_s = smem + 64 * ROWSTR;             // 32*580
    int*   pixl    = (int*)(patch_s + PXT * PSTR);   // 32 ints
    float* bias_s  = (float*)(pixl + PXT);           // 64 floats

    int bid = blockIdx.x;
    if (bid >= g_nchunks) return;    // uniform per-CTA exit (before any sync)
    int bkt  = g_chunk_bucket[bid];
    int base = g_chunk_base[bid];
    int npx  = g_chunk_cnt[bid];

    int tid  = threadIdx.x;
    int lane = tid & 31;
    int w    = tid >> 5;          // K-split warp id
    int rs   = lane & 7;          // rows rs + 8k
    int ps   = lane >> 3;         // px  ps + 4m

    if (tid < PXT) pixl[tid] = (tid < npx) ? g_pix[base + tid] : 0;
    __syncthreads();

    // --- stage 64 filter rows: float4 LDG + division-free scatter ---
    {
        const float4* embb4 = (const float4*)(emb + (size_t)bkt * EMB_ROW);
        int r = 0, c = tid << 2;
        #pragma unroll 4
        for (int i4 = tid; i4 < EMB_ROW / 4; i4 += 128) {
            float4 v = __ldg(embb4 + i4);
            float el[4] = {v.x, v.y, v.z, v.w};
            #pragma unroll
            for (int m = 0; m < 4; ++m) {
                int cc = c + m, rr = r;
                if (cc >= CKK1) { cc -= CKK1; rr++; }
                rows_s[rr * ROWSTR + cc] = el[m];
            }
            c += 512;
            if (c >= CKK1) { c -= CKK1; r++; }
        }
    }

    // --- patch build: decode (cin,ky,kx) once, then loop px ---
    {
        int ecol[5], ebase[5], edy[5], edx[5];
        #pragma unroll
        for (int jj = 0; jj < 5; ++jj) {
            int e = tid + 128 * jj;
            if (e > 576) e = 576;             // dup writes of 1.0 are benign
            ecol[jj] = e;
            if (e == 576) { ebase[jj] = -1; edy[jj] = 0; edx[jj] = 0; }
            else {
                int cin = e / 9, r = e - cin * 9;
                int ky = r / 3, kx = r - ky * 3;
                ebase[jj] = cin * NPIX; edy[jj] = ky - 1; edx[jj] = kx - 1;
            }
        }
        #pragma unroll 2
        for (int px = 0; px < PXT; ++px) {
            int p = pixl[px];
            int y = p >> 6, xx = p & 63;
            float* pd = patch_s + px * PSTR;
            #pragma unroll
            for (int jj = 0; jj < 5; ++jj) {
                float v;
                if (ebase[jj] < 0) v = 1.0f;
                else {
                    int yy = y + edy[jj], x2 = xx + edx[jj];
                    v = ((unsigned)yy < (unsigned)HWDIM &&
                         (unsigned)x2 < (unsigned)HWDIM)
                            ? g_h[ebase[jj] + yy * HWDIM + x2] : 0.0f;
                }
                pd[ecol[jj]] = v;
            }
        }
    }
    __syncthreads();

    // --- dynamic conv: 8 rows x 8 px, warps split K (36 c4 each) ---
    unsigned long long acc[8][8];
    #pragma unroll
    for (int k = 0; k < 8; ++k)
        #pragma unroll
        for (int m = 0; m < 8; ++m) acc[k][m] = 0ull;

    int c4beg = 36 * w;
    #pragma unroll 2
    for (int c4 = c4beg; c4 < c4beg + 36; ++c4) {
        ulonglong2 px[8];
        #pragma unroll
        for (int m = 0; m < 8; ++m)
            px[m] = *(const ulonglong2*)(patch_s + (ps + 4 * m) * PSTR + (c4 << 2));
        #pragma unroll
        for (int k = 0; k < 8; ++k) {
            ulonglong2 rv = *(const ulonglong2*)(rows_s + (rs + 8 * k) * ROWSTR + (c4 << 2));
            #pragma unroll
            for (int m = 0; m < 8; ++m) {
                acc[k][m] = ffma2(rv.x, px[m].x, acc[k][m]);
                acc[k][m] = ffma2(rv.y, px[m].y, acc[k][m]);
            }
        }
    }
    __syncthreads();                       // compute reads of rows_s done

    if (tid < CCH) bias_s[tid] = rows_s[tid * ROWSTR + 576];
    __syncthreads();                       // bias saved before overlay

    // write K-partials into (dead) rows region: part[w][row][px]
    float* part = rows_s;                  // 4 * 2048 floats
    #pragma unroll
    for (int k = 0; k < 8; ++k)
        #pragma unroll
        for (int m = 0; m < 8; ++m)
            part[w * 2048 + (rs + 8 * k) * 32 + (ps + 4 * m)] = hadd2(acc[k][m]);
    __syncthreads();

    float* srel = rows_s + 4 * 2048;             // 64*36 floats
    float* wTp  = srel + CCH * SSTR;             // 64*65 floats
    for (int e = tid; e < 2048; e += 128) {
        int row = e >> 5, px = e & 31;
        float s = part[e] + part[2048 + e] + part[4096 + e] + part[6144 + e];
        s = fmaf(bias_s[row], patch_s[px * PSTR + 576], s);
        srel[row * SSTR + px] = fmaxf(s, 0.0f);
    }
    // stage w2 transposed
    for (int i = tid; i < CCH * CCH; i += 128) {
        int oc = i >> 6, k2 = i & 63;
        wTp[k2 * WTSTR + oc] = __ldg(w2 + i);
    }
    __syncthreads();

    // --- 1x1 conv + bias + residual + final ReLU ---
    int ocg  = tid & 31;
    int pxg1 = tid >> 5;
    float accA[8], accB[8];
    float bA = b2[ocg], bB = b2[ocg + 32];
    #pragma unroll
    for (int jj = 0; jj < 8; ++jj) { accA[jj] = bA; accB[jj] = bB; }

    const float4* srl = (const float4*)(srel + pxg1 * 8);
    #pragma unroll 4
    for (int k = 0; k < CCH; ++k) {
        float wa = wTp[k * WTSTR + ocg];
        float wb = wTp[k * WTSTR + ocg + 32];
        float4 s0 = srl[k * (SSTR / 4)];
        float4 s1 = srl[k * (SSTR / 4) + 1];
        accA[0] = fmaf(wa, s0.x, accA[0]); accB[0] = fmaf(wb, s0.x, accB[0]);
        accA[1] = fmaf(wa, s0.y, accA[1]); accB[1] = fmaf(wb, s0.y, accB[1]);
        accA[2] = fmaf(wa, s0.z, accA[2]); accB[2] = fmaf(wb, s0.z, accB[2]);
        accA[3] = fmaf(wa, s0.w, accA[3]); accB[3] = fmaf(wb, s0.w, accB[3]);
        accA[4] = fmaf(wa, s1.x, accA[4]); accB[4] = fmaf(wb, s1.x, accB[4]);
        accA[5] = fmaf(wa, s1.y, accA[5]); accB[5] = fmaf(wb, s1.y, accB[5]);
        accA[6] = fmaf(wa, s1.z, accA[6]); accB[6] = fmaf(wb, s1.z, accB[6]);
        accA[7] = fmaf(wa, s1.w, accA[7]); accB[7] = fmaf(wb, s1.w, accB[7]);
    }
    #pragma unroll
    for (int jj = 0; jj < 8; ++jj) {
        int px = pxg1 * 8 + jj;
        if (px < npx) {
            int p   = pixl[px];
            int oiA = ocg * NPIX + p;
            int oiB = (ocg + 32) * NPIX + p;
            out[oiA] = fmaxf(accA[jj] + x[oiA], 0.0f);
            out[oiB] = fmaxf(accB[jj] + x[oiB], 0.0f);
        }
    }
}

// ---------------------------------------------------------------------------
extern "C" void kernel_launch(void* const* d_in, const int* in_sizes, int n_in,
                              void* d_out, int out_size) {
    const float* x       = (const float*)d_in[0];
    const int*   buckets = (const int*)  d_in[1];
    const float* w1      = (const float*)d_in[2];
    const float* b1      = (const float*)d_in[3];
    const float* emb     = (const float*)d_in[4];
    const float* w2      = (const float*)d_in[5];
    const float* b2      = (const float*)d_in[6];
    float*       out     = (float*)d_out;

    const int smem_bytes = (64 * ROWSTR + PXT * PSTR) * 4 + PXT * 4 + CCH * 4;
    cudaFuncSetAttribute(dyn_kernel,
                         cudaFuncAttributeMaxDynamicSharedMemorySize, smem_bytes);

    body1_kernel<<<256, 128>>>(x, w1, b1);
    prep_kernel<<<1, 256>>>(buckets);
    dyn_kernel<<<MAXCH, 128, smem_bytes>>>(emb, w2, b2, x, out);
}